// round 9
// baseline (speedup 1.0000x reference)
#include <cuda_runtime.h>

#define HALFW 6
#define MAXC  63
#define NK    21
#define NB    64
#define NC    256
#define NH    64
#define NW    64
#define HW    (NH * NW)
#define NBLK  512                 // (4, 64, 2)
#define FULLM 0xffffffffu

// Scratch (allocation-free rule: __device__ globals; zero-initialized)
__device__ float g_part[2][NB][4][NK];  // per-block raw box partial sums
__device__ int   g_done = 0;            // grid completion counter (self-resetting)

// ---------------------------------------------------------------------------
// Single fused kernel. grid = (4, 64, 2), block = 256.
//  - warp-autonomous prologue: keypoints in registers, line mask via ballot,
//    NO barriers before the load loop (warps start streaming immediately)
//  - threads channel-reduce only needed 128B lines (~93%) -- proven loop
//  - fm tile staged in smem; per-block 21 box partials -> g_part
//  - only the 8 storing threads fence; last of 512 blocks computes MSE
// ---------------------------------------------------------------------------
__global__ void __launch_bounds__(256) fused_kernel(
    const float* __restrict__ f1, const float* __restrict__ f2,
    const int* __restrict__ pre1, const int* __restrict__ pre2,
    float* __restrict__ out)
{
    const int t    = blockIdx.z;
    const int b    = blockIdx.y;
    const int tid  = threadIdx.x;
    const int warp = tid >> 5;
    const int lane = tid & 31;
    const int h0   = blockIdx.x * 16;         // this block's row base

    __shared__ __align__(16) float s_fm[16 * NW];  // fm tile (chan-mean), 4KB

    // ---- warp-autonomous prologue: keypoints + needed-line mask ----
    const int* __restrict__ pre = (t == 0) ? pre1 : pre2;
    int px = 0, py = 0;
    if (lane < NK) {
        px = __ldg(&pre[(b * NK + lane) * 2 + 0]);
        py = __ldg(&pre[(b * NK + lane) * 2 + 1]);
    }
    // lane evaluates line L=lane: row h0+(L>>1), half (L&1)
    {
        const int h  = h0 + (lane >> 1);
        const int c0 = (lane & 1) * 32;
        bool need = false;
#pragma unroll
        for (int k = 0; k < NK; ++k) {
            const int xk = __shfl_sync(FULLM, px, k);
            const int yk = __shfl_sync(FULLM, py, k);
            const int left  = max(xk - HALFW, 0);
            const int right = min(xk + HALFW, MAXC);   // exclusive
            const int down  = max(yk - HALFW, 0);
            const int up    = min(yk + HALFW, MAXC);   // exclusive
            need |= (h >= left) & (h < right) & (down < c0 + 32) & (up > c0);
        }
        const unsigned mask = __ballot_sync(FULLM, need);

        // ---- channel reduce over needed lines only (proven loop shape) ----
        const int nlines = __popc(mask);
        const int j      = tid >> 3;          // line slot 0..31
        const int f      = tid & 7;           // float4 within 128B line
        if (j < nlines) {
            const int line = __fns(mask, 0, j + 1);   // (j+1)-th set bit
            const int lr = line >> 1;
            const int c4 = (line & 1) * 8 + f;        // float4 col 0..15
            const int hw4 = (h0 + lr) * 16 + c4;

            const float4* __restrict__ f4 =
                reinterpret_cast<const float4*>(t == 0 ? f1 : f2);
            const float4* __restrict__ p = f4 + (size_t)b * NC * (HW / 4) + hw4;

            float4 acc = make_float4(0.f, 0.f, 0.f, 0.f);
#pragma unroll 8
            for (int c = 0; c < NC; ++c) {
                float4 v = p[(size_t)c * (HW / 4)];
                acc.x += v.x; acc.y += v.y; acc.z += v.z; acc.w += v.w;
            }
            const float sc = 1.0f / (float)NC;
            float4 o = make_float4(acc.x * sc, acc.y * sc, acc.z * sc, acc.w * sc);
            *reinterpret_cast<float4*>(&s_fm[lr * NW + c4 * 4]) = o;
        }
    }
    __syncthreads();                          // s_fm tile complete

    // ---- per-block box partials: warp-per-keypoint, div-free 12x12 ----
    for (int k = warp; k < NK; k += 8) {
        const int xk = __shfl_sync(FULLM, px, k);
        const int yk = __shfl_sync(FULLM, py, k);
        const int left  = max(xk - HALFW, 0);
        const int right = min(xk + HALFW, MAXC);
        const int down  = max(yk - HALFW, 0);
        const int up    = min(yk + HALFW, MAXC);
        const int rl = max(left, h0);
        const int rr = min(right, h0 + 16);
        const int nhl = rr - rl;              // may be <= 0
        const int nw  = up - down;            // 6..12

        float s = 0.f;
#pragma unroll
        for (int it = 0; it < 5; ++it) {
            const int idx = lane + 32 * it;   // 0..159
            const int r = idx / 12;           // constant divisor -> mul/shift
            const int c = idx - r * 12;
            if ((idx < 144) && (r < nhl) && (c < nw))
                s += s_fm[(rl - h0 + r) * NW + (down + c)];
        }
#pragma unroll
        for (int off = 16; off > 0; off >>= 1)
            s += __shfl_down_sync(FULLM, s, off);
        if (lane == 0)
            g_part[t][b][blockIdx.x][k] = s;  // every slot written each call
    }

    // ---- grid completion: only storing threads fence ----
    __shared__ int s_last;
    if (lane == 0) __threadfence();           // order this warp's g_part store
    __syncthreads();
    if (tid == 0)
        s_last = (atomicAdd(&g_done, 1) == NBLK - 1) ? 1 : 0;
    __syncthreads();
    if (!s_last) return;

    __threadfence();
    __shared__ float s_fea[2 * NK];
    for (int g = warp; g < 2 * NK; g += 8) {
        const int tt = g / NK;
        const int kk = g - tt * NK;
        const int* __restrict__ pp = (tt == 0) ? pre1 : pre2;
        float v = 0.f;
#pragma unroll
        for (int half = 0; half < 2; ++half) {
            const int bb = lane + 32 * half;
            const int x = pp[(bb * NK + kk) * 2 + 0];
            const int y = pp[(bb * NK + kk) * 2 + 1];
            const int cnt = (min(x + HALFW, MAXC) - max(x - HALFW, 0)) *
                            (min(y + HALFW, MAXC) - max(y - HALFW, 0));
            float ssum = 0.f;
#pragma unroll
            for (int xb = 0; xb < 4; ++xb)
                ssum += __ldcg(&g_part[tt][bb][xb][kk]);
            v += ssum * (1.0f / (float)cnt);
        }
#pragma unroll
        for (int off = 16; off > 0; off >>= 1)
            v += __shfl_down_sync(FULLM, v, off);
        if (lane == 0)
            s_fea[g] = v * (1.0f / (float)NB);
    }
    __syncthreads();
    if (tid == 0) {
        float acc2 = 0.f;
#pragma unroll
        for (int kk = 0; kk < NK; ++kk) {
            const float d = s_fea[kk] - 0.999f * s_fea[NK + kk];
            acc2 += d * d;
        }
        out[0] = acc2 * (1.0f / (float)NK);
        g_done = 0;                           // reset for next replay
    }
}

extern "C" void kernel_launch(void* const* d_in, const int* in_sizes, int n_in,
                              void* d_out, int out_size)
{
    const float* f1   = (const float*)d_in[0];
    const float* f2   = (const float*)d_in[1];
    const int*   pre1 = (const int*)d_in[2];
    const int*   pre2 = (const int*)d_in[3];

    fused_kernel<<<dim3(4, NB, 2), 256>>>(f1, f2, pre1, pre2, (float*)d_out);
}